// round 12
// baseline (speedup 1.0000x reference)
#include <cuda_runtime.h>
#include <math.h>

#define B_ 8
#define N_ 2048
#define F_ 256
#define K_ 205
#define ACAP 256
#define CSRCAP 128
#define SROWCAP 130
#define ROWS_ (B_*N_)

// output layout (floats): [xc | coarse | S | topi]
#define XC_OFF 0
#define CO_OFF ((size_t)B_*N_*F_)
#define SO_OFF (CO_OFF + (size_t)B_*N_*N_)
#define TI_OFF (SO_OFF + (size_t)B_*N_*N_)

// ---- static scratch ----
__device__ float g_t[ROWS_];
__device__ float g_radj[ROWS_];
__device__ float g_adiag[ROWS_];
__device__ float g_dg[ROWS_];
__device__ float g_alpha[ROWS_];
__device__ int   g_ccol[ROWS_*CSRCAP];
__device__ float g_cval[ROWS_*CSRCAP];
__device__ int   g_ccnt[ROWS_];
__device__ int   g_sj[ROWS_*SROWCAP];
__device__ float g_sv[ROWS_*SROWCAP];
__device__ int   g_scnt[ROWS_];
__device__ int   g_colid[B_*ACAP];
__device__ float g_w[B_*ACAP];
__device__ int   g_acnt[B_];
__device__ int   g_rank[ROWS_];
__device__ float g_T[(size_t)ROWS_*ACAP];

// ---- KA: {CSR+rowsum+diag+dg} | {t = x@W}  (R5-proven ballot compaction) ----
__global__ void kA(const float* __restrict__ adj, const float* __restrict__ x,
                   const float* __restrict__ W){
    int blk = blockIdx.x;
    int lane = threadIdx.x & 31;
    if (blk < 2048) {
        int row = blk * 8 + (threadIdx.x >> 5);
        int n = row % N_;
        const float4* ar4 = (const float4*)(adj + (size_t)row * N_);
        float sum = 0.f, diag = 0.f;
        int cnt = 0, base = row * CSRCAP;
        #pragma unroll 4
        for (int c4 = lane; c4 < N_/4; c4 += 32) {
            float4 a = ar4[c4];
            float va[4] = {a.x, a.y, a.z, a.w};
            int col0 = c4 * 4;
            sum += va[0] + va[1] + va[2] + va[3];
            if ((n >> 2) == c4) diag = va[n & 3];
            #pragma unroll
            for (int q = 0; q < 4; q++) {
                float v = va[q];
                unsigned msk = __ballot_sync(0xffffffffu, v != 0.f);
                if (v != 0.f) {
                    int pos = cnt + __popc(msk & ((1u << lane) - 1u));
                    if (pos < CSRCAP) { g_ccol[base + pos] = col0 + q; g_cval[base + pos] = v; }
                }
                cnt += __popc(msk);
            }
        }
        #pragma unroll
        for (int o = 16; o; o >>= 1) {
            sum  += __shfl_xor_sync(0xffffffffu, sum,  o);
            diag += __shfl_xor_sync(0xffffffffu, diag, o);
        }
        if (lane == 0) {
            g_radj[row] = sum;
            g_adiag[row] = diag;
            g_ccnt[row] = cnt < CSRCAP ? cnt : CSRCAP;
            g_dg[row] = rsqrtf(sum + 1.f);
        }
    } else {
        int row = (blk - 2048) * 8 + (threadIdx.x >> 5);
        const float4* xr4 = (const float4*)(x + (size_t)row * F_);
        const float4* W4 = (const float4*)W;
        float s = 0.f;
        #pragma unroll
        for (int f = lane; f < F_/4; f += 32) {
            float4 xv = xr4[f]; float4 wv = W4[f];
            s += xv.x*wv.x + xv.y*wv.y + xv.z*wv.z + xv.w*wv.w;
        }
        #pragma unroll
        for (int o = 16; o; o >>= 1) s += __shfl_xor_sync(0xffffffffu, s, o);
        if (lane == 0) g_t[row] = s;
    }
}

// ---- KB: alpha (bare) ----
__global__ void k_alpha(const float* __restrict__ bptr){
    int row = blockIdx.x * 8 + (threadIdx.x >> 5);
    int lane = threadIdx.x & 31;
    int bN = (row / N_) * N_;
    int base = row * CSRCAP;
    int cnt = g_ccnt[row];
    float s = 0.f;
    for (int e = lane; e < cnt; e += 32) {
        int m = g_ccol[base + e];
        s += g_cval[base + e] * __ldg(&g_dg[bN + m]) * __ldg(&g_t[bN + m]);
    }
    #pragma unroll
    for (int o = 16; o; o >>= 1) s += __shfl_xor_sync(0xffffffffu, s, o);
    if (lane == 0) {
        s += g_dg[row] * g_t[row];            // identity part of A_hat
        float pre = g_dg[row] * s + bptr[0];
        float z = pre * pre;
        g_alpha[row] = 1.f / (1.f + expf(-z));
    }
}

// ---- KC: per-batch top-K (bitonic, value desc / index asc) (bare) ----
__global__ void k_topk(float* __restrict__ out_ti){
    int b = blockIdx.x;
    int tid = threadIdx.x;
    __shared__ unsigned long long sk[N_];
    __shared__ float cutv;
    __shared__ int acnt;
    for (int i = tid; i < N_; i += 1024) {
        g_rank[b * N_ + i] = -1;
        float v = g_alpha[b * N_ + i];
        unsigned u = __float_as_uint(v);
        u = (u & 0x80000000u) ? ~u : (u | 0x80000000u);
        sk[i] = ((unsigned long long)(~u) << 32) | (unsigned)i;
    }
    __syncthreads();
    for (int k = 2; k <= N_; k <<= 1) {
        for (int j = k >> 1; j > 0; j >>= 1) {
            for (int t = tid; t < N_; t += 1024) {
                int ixj = t ^ j;
                if (ixj > t) {
                    bool up = ((t & k) == 0);
                    unsigned long long a = sk[t], c = sk[ixj];
                    if ((a > c) == up) { sk[t] = c; sk[ixj] = a; }
                }
            }
            __syncthreads();
        }
    }
    if (tid == 0) {
        int idxK = (int)(sk[K_ - 1] & 0xffffffffu);
        cutv = g_alpha[b * N_ + idxK];
        int A = K_;
        while (A < ACAP) {
            int id = (int)(sk[A] & 0xffffffffu);
            float v = g_alpha[b * N_ + id];
            if (v + 1e-7f - cutv > 0.f) A++; else break;
        }
        acnt = A;
        g_acnt[b] = A;
    }
    __syncthreads();
    for (int j = tid; j < acnt; j += 1024) {
        int id = (int)(sk[j] & 0xffffffffu);
        g_colid[b * ACAP + j] = id;
        g_w[b * ACAP + j] = g_alpha[b * N_ + id] + 1e-7f - cutv;
        g_rank[b * N_ + id] = j;
    }
    for (int j = tid; j < K_; j += 1024) {
        int id = (int)(sk[j] & 0xffffffffu);
        out_ti[b * K_ + j] = (float)id;
    }
}

// ---- KD: build normalized S rows; zero + scatter fused (S written ONCE) ----
__global__ void __launch_bounds__(256) k_sbuild(float* __restrict__ S_out){
    int w = threadIdx.x >> 5;
    int row = blockIdx.x * 8 + w;
    int lane = threadIdx.x & 31;
    __shared__ int   scol[8][SROWCAP];
    __shared__ float sval[8][SROWCAP];

    // (1) dense zero of this row — independent stores, issued first
    float4* rowp = (float4*)(S_out + (size_t)row * N_);
    float4 z = make_float4(0.f, 0.f, 0.f, 0.f);
    #pragma unroll
    for (int t = 0; t < 16; t++) rowp[t * 32 + lane] = z;

    int b = row / N_, n = row % N_;
    int sc = 0;
    int sbase = row * SROWCAP;

    if (g_radj[row] > 0.f) {
        float dgn = g_dg[row];
        int cnt = g_ccnt[row], base = row * CSRCAP;
        bool hasdiag = (g_adiag[row] != 0.f);
        // (2) pass 1: unnormalized row sum
        float rs = 0.f;
        for (int e = lane; e < cnt; e += 32) {
            int m = g_ccol[base + e];
            int j = g_rank[b * N_ + m];
            if (j >= 0) {
                float ahat = g_cval[base + e] + (m == n ? 1.f : 0.f);
                rs += dgn * ahat * g_dg[b * N_ + m] * g_w[b * ACAP + j];
            }
        }
        if (!hasdiag && lane == 0) {
            int j = g_rank[row];
            if (j >= 0) rs += dgn * dgn * g_w[b * ACAP + j];
        }
        #pragma unroll
        for (int o = 16; o; o >>= 1) rs += __shfl_xor_sync(0xffffffffu, rs, o);
        float inv = 1.f / fmaxf(rs, 1e-12f);
        // pass 2: emit entries into smem + global sparse lists
        for (int c = 0; c < cnt; c += 32) {
            int e = c + lane;
            bool act = false; int j = -1, m = -1; float v = 0.f;
            if (e < cnt) {
                m = g_ccol[base + e];
                j = g_rank[b * N_ + m];
                if (j >= 0) {
                    act = true;
                    float ahat = g_cval[base + e] + (m == n ? 1.f : 0.f);
                    v = dgn * ahat * g_dg[b * N_ + m] * g_w[b * ACAP + j] * inv;
                }
            }
            unsigned msk = __ballot_sync(0xffffffffu, act);
            if (act) {
                int pos = sc + __popc(msk & ((1u << lane) - 1u));
                if (pos < SROWCAP) {
                    g_sj[sbase + pos] = j; g_sv[sbase + pos] = v;
                    scol[w][pos] = m;  sval[w][pos] = v;
                }
            }
            sc += __popc(msk);
        }
        if (!hasdiag) {
            int add = 0;
            if (lane == 0) {
                int j = g_rank[row];
                if (j >= 0) {
                    float v = dgn * dgn * g_w[b * ACAP + j] * inv;
                    if (sc < SROWCAP) {
                        g_sj[sbase + sc] = j; g_sv[sbase + sc] = v;
                        scol[w][sc] = n;  sval[w][sc] = v;
                    }
                    add = 1;
                }
            }
            sc += __shfl_sync(0xffffffffu, add, 0);
        }
        if (sc > SROWCAP) sc = SROWCAP;
    }
    if (lane == 0) g_scnt[row] = sc;

    // (3) order zeros before scatter within the warp, then (4) scatter entries
    __syncwarp();
    float* rowf = S_out + (size_t)row * N_;
    for (int e = lane; e < sc; e += 32)
        rowf[scol[w][e]] = sval[w][e];
}

// ---- KE: T[n,:] = sum_k adj[n,k]*Srow[k]  (warp/row, smem atomics) [R5 exact] ----
__global__ void k_T(){
    int w = threadIdx.x >> 5;
    int row = blockIdx.x * 8 + w;
    int lane = threadIdx.x & 31;
    __shared__ float acc[8][ACAP];
    float* a = acc[w];
    for (int i = lane; i < ACAP; i += 32) a[i] = 0.f;
    __syncwarp();
    int b = row / N_;
    int cnt = g_ccnt[row], base = row * CSRCAP;
    for (int e = lane; e < cnt; e += 32) {
        int k = g_ccol[base + e];
        float av = g_cval[base + e];
        size_t krow = (size_t)b * N_ + k;
        int sb = (int)krow * SROWCAP;
        int sc = g_scnt[krow];
        for (int q = 0; q < sc; q++)
            atomicAdd(&a[g_sj[sb + q]], av * g_sv[sb + q]);
    }
    __syncwarp();
    int A = g_acnt[b];
    float* Trow = g_T + (size_t)row * ACAP;
    for (int j = lane; j < A; j += 32) Trow[j] = a[j];
}

// ---- KF: sole writer of the front: dense coarse row + xc row per (m, b) ----
__global__ void __launch_bounds__(256) k_cx(
        const float* __restrict__ x, const float* __restrict__ S_out,
        float* __restrict__ out_co, float* __restrict__ out_xc){
    int b = blockIdx.y;
    int m = blockIdx.x;
    int tid = threadIdx.x;
    size_t bN = (size_t)b * N_;
    size_t mrow = bN + m;
    float4* co4 = (float4*)(out_co + mrow * N_);

    if (g_rank[mrow] < 0) {
        // inactive column m: whole coarse row and xc row are zero
        float4 z = make_float4(0.f, 0.f, 0.f, 0.f);
        co4[tid] = z;
        co4[tid + 256] = z;
        out_xc[mrow * F_ + tid] = 0.f;
        return;
    }

    int A = g_acnt[b];
    __shared__ int   sn[CSRCAP + 1];
    __shared__ float sv[CSRCAP + 1];
    __shared__ float sacc[ACAP];
    if (tid < ACAP) sacc[tid] = 0.f;

    int cnt = g_ccnt[mrow], base = (int)mrow * CSRCAP;
    if (tid < cnt) {
        int n2 = g_ccol[base + tid];
        sn[tid] = n2;
        sv[tid] = S_out[(bN + n2) * N_ + m];   // symmetry: col m pattern = row m
    }
    int tot = cnt;
    if (g_adiag[mrow] == 0.f) {
        if (tid == 0) { sn[cnt] = m; sv[cnt] = S_out[mrow * N_ + m]; }
        tot = cnt + 1;
    }
    __syncthreads();
    // x_c: tid = feature index (F_ == blockDim.x == 256)
    {
        float acc = 0.f;
        for (int e = 0; e < tot; e++)
            acc += sv[e] * x[(bN + sn[e]) * F_ + tid];
        out_xc[mrow * F_ + tid] = acc;
    }
    // coarse values in rank space -> smem
    if (tid < A) {
        float acc = 0.f;
        for (int e = 0; e < tot; e++)
            acc += sv[e] * g_T[(bN + sn[e]) * ACAP + tid];
        sacc[tid] = floorf(acc * 10000.0f) / 10000.0f;
    }
    __syncthreads();
    // dense coarse row write: rank-gather (zeros where inactive)
    const int* rk = g_rank + bN;
    #pragma unroll
    for (int h = 0; h < 2; h++) {
        int c4 = tid + h * 256;
        int l0 = c4 * 4;
        float4 o;
        #pragma unroll
        for (int q = 0; q < 4; q++) {
            int j = rk[l0 + q];
            ((float*)&o)[q] = (j >= 0) ? sacc[j] : 0.f;
        }
        co4[c4] = o;
    }
}

extern "C" void kernel_launch(void* const* d_in, const int* in_sizes, int n_in,
                              void* d_out, int out_size) {
    const float* x   = (const float*)d_in[0];
    const float* adj = (const float*)d_in[1];
    const float* W   = (const float*)d_in[2];
    const float* bb  = (const float*)d_in[3];
    float* out = (float*)d_out;

    kA      <<<4096, 256>>>(adj, x, W);
    k_alpha <<<2048, 256>>>(bb);
    k_topk  <<<B_, 1024>>>(out + TI_OFF);
    k_sbuild<<<ROWS_ / 8, 256>>>(out + SO_OFF);
    k_T     <<<ROWS_ / 8, 256>>>();
    dim3 gblk(N_, B_);
    k_cx    <<<gblk, 256>>>(x, out + SO_OFF, out + CO_OFF, out + XC_OFF);
}

// round 14
// speedup vs baseline: 1.0803x; 1.0803x over previous
#include <cuda_runtime.h>
#include <math.h>

#define B_ 8
#define N_ 2048
#define F_ 256
#define K_ 205
#define ACAP 256
#define CSRCAP 128
#define SROWCAP 130
#define ROWS_ (B_*N_)

// output layout (floats): [xc | coarse | S | topi]
#define XC_OFF 0
#define CO_OFF ((size_t)B_*N_*F_)
#define SO_OFF (CO_OFF + (size_t)B_*N_*N_)
#define TI_OFF (SO_OFF + (size_t)B_*N_*N_)
#define FRONT4 (SO_OFF/4)              // float4 count of [xc+coarse)
#define FHALF  (FRONT4/2)
#define SREG4  (((size_t)B_*N_*N_)/4)  // float4 count of S region

#define TZB 1024   // zero blocks appended to k_topk (1024 thr) -> S region

// ---- static scratch ----
__device__ float g_t[ROWS_];
__device__ float g_radj[ROWS_];
__device__ float g_adiag[ROWS_];
__device__ float g_dg[ROWS_];
__device__ float g_alpha[ROWS_];
__device__ int   g_ccol[ROWS_*CSRCAP];
__device__ float g_cval[ROWS_*CSRCAP];
__device__ int   g_ccnt[ROWS_];
__device__ int   g_sj[ROWS_*SROWCAP];
__device__ float g_sv[ROWS_*SROWCAP];
__device__ int   g_scnt[ROWS_];
__device__ int   g_colid[B_*ACAP];
__device__ float g_w[B_*ACAP];
__device__ int   g_acnt[B_];
__device__ int   g_rank[ROWS_];
__device__ float g_T[(size_t)ROWS_*ACAP];

__device__ __forceinline__ void zero_range(float4* o4, size_t begin, size_t end,
                                           size_t tidx, size_t nthreads){
    float4 z = make_float4(0.f,0.f,0.f,0.f);
    for (size_t i = begin + tidx; i < end; i += nthreads) o4[i] = z;
}

// ---- KA: {CSR+rowsum+diag+dg} | {t = x@W}  (R5 exact) ----
__global__ void kA(const float* __restrict__ adj, const float* __restrict__ x,
                   const float* __restrict__ W){
    int blk = blockIdx.x;
    int lane = threadIdx.x & 31;
    if (blk < 2048) {
        int row = blk * 8 + (threadIdx.x >> 5);
        int n = row % N_;
        const float4* ar4 = (const float4*)(adj + (size_t)row * N_);
        float sum = 0.f, diag = 0.f;
        int cnt = 0, base = row * CSRCAP;
        #pragma unroll 4
        for (int c4 = lane; c4 < N_/4; c4 += 32) {
            float4 a = ar4[c4];
            float va[4] = {a.x, a.y, a.z, a.w};
            int col0 = c4 * 4;
            sum += va[0] + va[1] + va[2] + va[3];
            if ((n >> 2) == c4) diag = va[n & 3];
            #pragma unroll
            for (int q = 0; q < 4; q++) {
                float v = va[q];
                unsigned msk = __ballot_sync(0xffffffffu, v != 0.f);
                if (v != 0.f) {
                    int pos = cnt + __popc(msk & ((1u << lane) - 1u));
                    if (pos < CSRCAP) { g_ccol[base + pos] = col0 + q; g_cval[base + pos] = v; }
                }
                cnt += __popc(msk);
            }
        }
        #pragma unroll
        for (int o = 16; o; o >>= 1) {
            sum  += __shfl_xor_sync(0xffffffffu, sum,  o);
            diag += __shfl_xor_sync(0xffffffffu, diag, o);
        }
        if (lane == 0) {
            g_radj[row] = sum;
            g_adiag[row] = diag;
            g_ccnt[row] = cnt < CSRCAP ? cnt : CSRCAP;
            g_dg[row] = rsqrtf(sum + 1.f);
        }
    } else {
        int row = (blk - 2048) * 8 + (threadIdx.x >> 5);
        const float4* xr4 = (const float4*)(x + (size_t)row * F_);
        const float4* W4 = (const float4*)W;
        float s = 0.f;
        #pragma unroll
        for (int f = lane; f < F_/4; f += 32) {
            float4 xv = xr4[f]; float4 wv = W4[f];
            s += xv.x*wv.x + xv.y*wv.y + xv.z*wv.z + xv.w*wv.w;
        }
        #pragma unroll
        for (int o = 16; o; o >>= 1) s += __shfl_xor_sync(0xffffffffu, s, o);
        if (lane == 0) g_t[row] = s;
    }
}

// ---- KB: alpha (bare) ----
__global__ void k_alpha(const float* __restrict__ bptr){
    int row = blockIdx.x * 8 + (threadIdx.x >> 5);
    int lane = threadIdx.x & 31;
    int bN = (row / N_) * N_;
    int base = row * CSRCAP;
    int cnt = g_ccnt[row];
    float s = 0.f;
    for (int e = lane; e < cnt; e += 32) {
        int m = g_ccol[base + e];
        s += g_cval[base + e] * __ldg(&g_dg[bN + m]) * __ldg(&g_t[bN + m]);
    }
    #pragma unroll
    for (int o = 16; o; o >>= 1) s += __shfl_xor_sync(0xffffffffu, s, o);
    if (lane == 0) {
        s += g_dg[row] * g_t[row];            // identity part of A_hat
        float pre = g_dg[row] * s + bptr[0];
        float z = pre * pre;
        g_alpha[row] = 1.f / (1.f + expf(-z));
    }
}

// ---- KC: per-batch top-K (bitonic) | zero S region (8 compute blocks -> no tail wave) ----
__global__ void k_topk(float* __restrict__ out_all){
    int blk = blockIdx.x;
    int tid = threadIdx.x;
    if (blk >= B_) {
        zero_range((float4*)(out_all + SO_OFF), 0, SREG4,
                   (size_t)(blk - B_) * 1024 + tid, (size_t)TZB * 1024);
        return;
    }
    int b = blk;
    float* out_ti = out_all + TI_OFF;
    __shared__ unsigned long long sk[N_];
    __shared__ float cutv;
    __shared__ int acnt;
    for (int i = tid; i < N_; i += 1024) {
        g_rank[b * N_ + i] = -1;
        float v = g_alpha[b * N_ + i];
        unsigned u = __float_as_uint(v);
        u = (u & 0x80000000u) ? ~u : (u | 0x80000000u);
        sk[i] = ((unsigned long long)(~u) << 32) | (unsigned)i;
    }
    __syncthreads();
    for (int k = 2; k <= N_; k <<= 1) {
        for (int j = k >> 1; j > 0; j >>= 1) {
            for (int t = tid; t < N_; t += 1024) {
                int ixj = t ^ j;
                if (ixj > t) {
                    bool up = ((t & k) == 0);
                    unsigned long long a = sk[t], c = sk[ixj];
                    if ((a > c) == up) { sk[t] = c; sk[ixj] = a; }
                }
            }
            __syncthreads();
        }
    }
    if (tid == 0) {
        int idxK = (int)(sk[K_ - 1] & 0xffffffffu);
        cutv = g_alpha[b * N_ + idxK];
        int A = K_;
        while (A < ACAP) {
            int id = (int)(sk[A] & 0xffffffffu);
            float v = g_alpha[b * N_ + id];
            if (v + 1e-7f - cutv > 0.f) A++; else break;
        }
        acnt = A;
        g_acnt[b] = A;
    }
    __syncthreads();
    for (int j = tid; j < acnt; j += 1024) {
        int id = (int)(sk[j] & 0xffffffffu);
        g_colid[b * ACAP + j] = id;
        g_w[b * ACAP + j] = g_alpha[b * N_ + id] + 1e-7f - cutv;
        g_rank[b * N_ + id] = j;
    }
    for (int j = tid; j < K_; j += 1024) {
        int id = (int)(sk[j] & 0xffffffffu);
        out_ti[b * K_ + j] = (float)id;
    }
}

// ---- KD: S rows scatter (R5 exact) | zero front half 1 (INTERLEAVED, R9-proven) ----
__global__ void k_sbuild(float* __restrict__ out_all){
    if (blockIdx.x & 1) {
        zero_range((float4*)out_all, 0, FHALF,
                   (size_t)(blockIdx.x >> 1) * 256 + threadIdx.x, (size_t)2048 * 256);
        return;
    }
    float* S_out = out_all + SO_OFF;
    int row = (blockIdx.x >> 1) * 8 + (threadIdx.x >> 5);
    int lane = threadIdx.x & 31;
    int b = row / N_, n = row % N_;
    if (g_radj[row] <= 0.f) {
        if (lane == 0) g_scnt[row] = 0;
        return;
    }
    float dgn = g_dg[row];
    int cnt = g_ccnt[row], base = row * CSRCAP;
    bool hasdiag = (g_adiag[row] != 0.f);
    float rs = 0.f;
    for (int e = lane; e < cnt; e += 32) {
        int m = g_ccol[base + e];
        int j = g_rank[b * N_ + m];
        if (j >= 0) {
            float ahat = g_cval[base + e] + (m == n ? 1.f : 0.f);
            rs += dgn * ahat * g_dg[b * N_ + m] * g_w[b * ACAP + j];
        }
    }
    if (!hasdiag && lane == 0) {
        int j = g_rank[row];
        if (j >= 0) rs += dgn * dgn * g_w[b * ACAP + j];
    }
    #pragma unroll
    for (int o = 16; o; o >>= 1) rs += __shfl_xor_sync(0xffffffffu, rs, o);
    float inv = 1.f / fmaxf(rs, 1e-12f);
    int sc = 0, sbase = row * SROWCAP;
    for (int c = 0; c < cnt; c += 32) {
        int e = c + lane;
        bool act = false; int j = -1, m = -1; float v = 0.f;
        if (e < cnt) {
            m = g_ccol[base + e];
            j = g_rank[b * N_ + m];
            if (j >= 0) {
                act = true;
                float ahat = g_cval[base + e] + (m == n ? 1.f : 0.f);
                v = dgn * ahat * g_dg[b * N_ + m] * g_w[b * ACAP + j] * inv;
            }
        }
        unsigned msk = __ballot_sync(0xffffffffu, act);
        if (act) {
            int pos = sc + __popc(msk & ((1u << lane) - 1u));
            if (pos < SROWCAP) { g_sj[sbase + pos] = j; g_sv[sbase + pos] = v; }
            S_out[(size_t)row * N_ + m] = v;
        }
        sc += __popc(msk);
    }
    if (!hasdiag) {
        int add = 0;
        if (lane == 0) {
            int j = g_rank[row];
            if (j >= 0) {
                float v = dgn * dgn * g_w[b * ACAP + j] * inv;
                if (sc < SROWCAP) { g_sj[sbase + sc] = j; g_sv[sbase + sc] = v; }
                S_out[(size_t)row * N_ + n] = v;
                add = 1;
            }
        }
        sc += __shfl_sync(0xffffffffu, add, 0);
    }
    if (lane == 0) g_scnt[row] = sc < SROWCAP ? sc : SROWCAP;
}

// ---- KE: T (R5 exact) | zero front half 2 (INTERLEAVED) ----
__global__ void k_T(float* __restrict__ out_all){
    if (blockIdx.x & 1) {
        zero_range((float4*)out_all, FHALF, FRONT4,
                   (size_t)(blockIdx.x >> 1) * 256 + threadIdx.x, (size_t)2048 * 256);
        return;
    }
    int w = threadIdx.x >> 5;
    int row = (blockIdx.x >> 1) * 8 + w;
    int lane = threadIdx.x & 31;
    __shared__ float acc[8][ACAP];
    float* a = acc[w];
    for (int i = lane; i < ACAP; i += 32) a[i] = 0.f;
    __syncwarp();
    int b = row / N_;
    int cnt = g_ccnt[row], base = row * CSRCAP;
    for (int e = lane; e < cnt; e += 32) {
        int k = g_ccol[base + e];
        float av = g_cval[base + e];
        size_t krow = (size_t)b * N_ + k;
        int sb = (int)krow * SROWCAP;
        int sc = g_scnt[krow];
        for (int q = 0; q < sc; q++)
            atomicAdd(&a[g_sj[sb + q]], av * g_sv[sb + q]);
    }
    __syncwarp();
    int A = g_acnt[b];
    float* Trow = g_T + (size_t)row * ACAP;
    for (int j = lane; j < A; j += 32) Trow[j] = a[j];
}

// ---- KF: fused coarse + x_c (R5 exact) ----
__global__ void __launch_bounds__(256) k_cx(
        const float* __restrict__ x, const float* __restrict__ S_out,
        float* __restrict__ out_co, float* __restrict__ out_xc){
    int b = blockIdx.y;
    int jm = blockIdx.x;
    int A = g_acnt[b];
    if (jm >= A) return;
    int tid = threadIdx.x;
    int m = g_colid[b * ACAP + jm];
    size_t bN = (size_t)b * N_;
    size_t mrow = bN + m;
    __shared__ int   sn[CSRCAP + 1];
    __shared__ float sv[CSRCAP + 1];
    int cnt = g_ccnt[mrow], base = (int)mrow * CSRCAP;
    if (tid < cnt) {
        int n2 = g_ccol[base + tid];
        sn[tid] = n2;
        sv[tid] = S_out[(bN + n2) * N_ + m];   // symmetry: col m pattern = row m
    }
    int tot = cnt;
    if (g_adiag[mrow] == 0.f) {
        if (tid == 0) { sn[cnt] = m; sv[cnt] = S_out[mrow * N_ + m]; }
        tot = cnt + 1;
    }
    __syncthreads();
    // x_c: tid = feature index (F_ == blockDim.x == 256)
    {
        float acc = 0.f;
        for (int e = 0; e < tot; e++)
            acc += sv[e] * x[(bN + sn[e]) * F_ + tid];
        out_xc[mrow * F_ + tid] = acc;
    }
    // coarse: active block column jm, all active rows j (A <= 256 == blockDim)
    if (tid < A) {
        float acc = 0.f;
        for (int e = 0; e < tot; e++)
            acc += sv[e] * g_T[(bN + sn[e]) * ACAP + tid];
        float c = floorf(acc * 10000.0f) / 10000.0f;
        int l = g_colid[b * ACAP + tid];
        out_co[mrow * N_ + l] = c;
    }
}

extern "C" void kernel_launch(void* const* d_in, const int* in_sizes, int n_in,
                              void* d_out, int out_size) {
    const float* x   = (const float*)d_in[0];
    const float* adj = (const float*)d_in[1];
    const float* W   = (const float*)d_in[2];
    const float* bb  = (const float*)d_in[3];
    float* out = (float*)d_out;

    kA      <<<4096, 256>>>(adj, x, W);
    k_alpha <<<2048, 256>>>(bb);
    k_topk  <<<B_ + TZB, 1024>>>(out);
    k_sbuild<<<4096, 256>>>(out);
    k_T     <<<4096, 256>>>(out);
    dim3 gblk(ACAP, B_);
    k_cx    <<<gblk, 256>>>(x, out + SO_OFF, out + CO_OFF, out + XC_OFF);
}

// round 15
// speedup vs baseline: 1.1036x; 1.0216x over previous
#include <cuda_runtime.h>
#include <math.h>

#define B_ 8
#define N_ 2048
#define F_ 256
#define K_ 205
#define ACAP 256
#define CSRCAP 128
#define SROWCAP 130
#define ROWS_ (B_*N_)

// output layout (floats): [xc | coarse | S | topi]
#define XC_OFF 0
#define CO_OFF ((size_t)B_*N_*F_)
#define SO_OFF (CO_OFF + (size_t)B_*N_*N_)
#define TI_OFF (SO_OFF + (size_t)B_*N_*N_)
#define FRONT4 (SO_OFF/4)              // float4 count of [xc+coarse)
#define SREG4  (((size_t)B_*N_*N_)/4)  // float4 count of S region

#define AZB 8192   // zero blocks appended to k_alpha (256 thr) -> S region
#define TZB 2048   // zero blocks appended to k_topk  (1024 thr) -> front

// ---- static scratch ----
__device__ float g_t[ROWS_];
__device__ float g_radj[ROWS_];
__device__ float g_adiag[ROWS_];
__device__ float g_dg[ROWS_];
__device__ float g_alpha[ROWS_];
__device__ int   g_ccol[ROWS_*CSRCAP];
__device__ float g_cval[ROWS_*CSRCAP];
__device__ int   g_ccnt[ROWS_];
__device__ int   g_sj[ROWS_*SROWCAP];
__device__ float g_sv[ROWS_*SROWCAP];
__device__ int   g_scnt[ROWS_];
__device__ int   g_colid[B_*ACAP];
__device__ float g_w[B_*ACAP];
__device__ int   g_acnt[B_];
__device__ int   g_rank[ROWS_];
__device__ float g_T[(size_t)ROWS_*ACAP];

// ---- KA: block-per-row CSR (high-MLP, scan compaction) | {t = x@W} ----
__global__ void __launch_bounds__(256) kA(const float* __restrict__ adj,
                                          const float* __restrict__ x,
                                          const float* __restrict__ W){
    int blk = blockIdx.x;
    int lane = threadIdx.x & 31;
    if (blk < ROWS_) {
        int row = blk;
        int tid = threadIdx.x;
        int w = tid >> 5;
        int n = row % N_;
        const float4* ar4 = (const float4*)(adj + (size_t)row * N_);
        // each thread owns 8 contiguous columns: two back-to-back float4 loads
        float4 a0 = ar4[tid * 2];
        float4 a1 = ar4[tid * 2 + 1];
        float va[8] = {a0.x, a0.y, a0.z, a0.w, a1.x, a1.y, a1.z, a1.w};
        float s = ((va[0] + va[1]) + (va[2] + va[3]))
                + ((va[4] + va[5]) + (va[6] + va[7]));
        int c = 0;
        #pragma unroll
        for (int q = 0; q < 8; q++) c += (va[q] != 0.f);

        __shared__ float sdiag;
        __shared__ int   wtot[8];
        __shared__ float wsum[8];
        int c0 = tid * 8;
        if (n >= c0 && n < c0 + 8) sdiag = va[n - c0];   // exactly one thread

        // warp-inclusive scan of counts (order = column order)
        int inc = c;
        #pragma unroll
        for (int d = 1; d < 32; d <<= 1) {
            int v = __shfl_up_sync(0xffffffffu, inc, d);
            if (lane >= d) inc += v;
        }
        // warp sum reduce
        float ws = s;
        #pragma unroll
        for (int o = 16; o; o >>= 1) ws += __shfl_xor_sync(0xffffffffu, ws, o);
        if (lane == 31) wtot[w] = inc;
        if (lane == 0)  wsum[w] = ws;
        __syncthreads();
        int woff = 0;
        #pragma unroll
        for (int i = 0; i < 8; i++) if (i < w) woff += wtot[i];
        int pos = woff + inc - c;
        int base = row * CSRCAP;
        #pragma unroll
        for (int q = 0; q < 8; q++) {
            if (va[q] != 0.f) {
                if (pos < CSRCAP) { g_ccol[base + pos] = c0 + q; g_cval[base + pos] = va[q]; }
                pos++;
            }
        }
        if (tid == 0) {
            float sum = ((wsum[0] + wsum[1]) + (wsum[2] + wsum[3]))
                      + ((wsum[4] + wsum[5]) + (wsum[6] + wsum[7]));
            int total = wtot[0] + wtot[1] + wtot[2] + wtot[3]
                      + wtot[4] + wtot[5] + wtot[6] + wtot[7];
            g_radj[row] = sum;
            g_adiag[row] = sdiag;
            g_ccnt[row] = total < CSRCAP ? total : CSRCAP;
            g_dg[row] = rsqrtf(sum + 1.f);
        }
    } else {
        // t = x @ W, one warp per row (float4)  [R5 exact]
        int row = (blk - ROWS_) * 8 + (threadIdx.x >> 5);
        const float4* xr4 = (const float4*)(x + (size_t)row * F_);
        const float4* W4 = (const float4*)W;
        float s = 0.f;
        #pragma unroll
        for (int f = lane; f < F_/4; f += 32) {
            float4 xv = xr4[f]; float4 wv = W4[f];
            s += xv.x*wv.x + xv.y*wv.y + xv.z*wv.z + xv.w*wv.w;
        }
        #pragma unroll
        for (int o = 16; o; o >>= 1) s += __shfl_xor_sync(0xffffffffu, s, o);
        if (lane == 0) g_t[row] = s;
    }
}

// ---- KB: alpha | zero S region  [R5 exact] ----
__global__ void k_alpha(const float* __restrict__ bptr, float* __restrict__ S_out){
    int blk = blockIdx.x;
    if (blk >= 2048) {
        size_t i = (size_t)(blk - 2048) * 256 + threadIdx.x;
        float4 z = make_float4(0.f,0.f,0.f,0.f);
        float4* o4 = (float4*)S_out;
        size_t stride = (size_t)AZB * 256;
        for (; i < SREG4; i += stride) o4[i] = z;
        return;
    }
    int row = blk * 8 + (threadIdx.x >> 5);
    int lane = threadIdx.x & 31;
    int bN = (row / N_) * N_;
    int base = row * CSRCAP;
    int cnt = g_ccnt[row];
    float s = 0.f;
    for (int e = lane; e < cnt; e += 32) {
        int m = g_ccol[base + e];
        s += g_cval[base + e] * __ldg(&g_dg[bN + m]) * __ldg(&g_t[bN + m]);
    }
    #pragma unroll
    for (int o = 16; o; o >>= 1) s += __shfl_xor_sync(0xffffffffu, s, o);
    if (lane == 0) {
        s += g_dg[row] * g_t[row];            // identity part of A_hat
        float pre = g_dg[row] * s + bptr[0];
        float z = pre * pre;
        g_alpha[row] = 1.f / (1.f + expf(-z));
    }
}

// ---- KC: per-batch top-K (bitonic) | zero front  [R5 exact] ----
__global__ void k_topk(float* __restrict__ out_all){
    int blk = blockIdx.x;
    int tid = threadIdx.x;
    if (blk >= B_) {
        size_t i = (size_t)(blk - B_) * 1024 + tid;
        float4 z = make_float4(0.f,0.f,0.f,0.f);
        float4* o4 = (float4*)out_all;
        size_t stride = (size_t)TZB * 1024;
        for (; i < FRONT4; i += stride) o4[i] = z;
        return;
    }
    int b = blk;
    float* out_ti = out_all + TI_OFF;
    __shared__ unsigned long long sk[N_];
    __shared__ float cutv;
    __shared__ int acnt;
    for (int i = tid; i < N_; i += 1024) {
        g_rank[b * N_ + i] = -1;
        float v = g_alpha[b * N_ + i];
        unsigned u = __float_as_uint(v);
        u = (u & 0x80000000u) ? ~u : (u | 0x80000000u);
        sk[i] = ((unsigned long long)(~u) << 32) | (unsigned)i;
    }
    __syncthreads();
    for (int k = 2; k <= N_; k <<= 1) {
        for (int j = k >> 1; j > 0; j >>= 1) {
            for (int t = tid; t < N_; t += 1024) {
                int ixj = t ^ j;
                if (ixj > t) {
                    bool up = ((t & k) == 0);
                    unsigned long long a = sk[t], c = sk[ixj];
                    if ((a > c) == up) { sk[t] = c; sk[ixj] = a; }
                }
            }
            __syncthreads();
        }
    }
    if (tid == 0) {
        int idxK = (int)(sk[K_ - 1] & 0xffffffffu);
        cutv = g_alpha[b * N_ + idxK];
        int A = K_;
        while (A < ACAP) {
            int id = (int)(sk[A] & 0xffffffffu);
            float v = g_alpha[b * N_ + id];
            if (v + 1e-7f - cutv > 0.f) A++; else break;
        }
        acnt = A;
        g_acnt[b] = A;
    }
    __syncthreads();
    for (int j = tid; j < acnt; j += 1024) {
        int id = (int)(sk[j] & 0xffffffffu);
        g_colid[b * ACAP + j] = id;
        g_w[b * ACAP + j] = g_alpha[b * N_ + id] + 1e-7f - cutv;
        g_rank[b * N_ + id] = j;
    }
    for (int j = tid; j < K_; j += 1024) {
        int id = (int)(sk[j] & 0xffffffffu);
        out_ti[b * K_ + j] = (float)id;
    }
}

// ---- KD: build normalized S rows (scatter into zeroed S)  [R5 exact] ----
__global__ void k_sbuild(float* __restrict__ S_out){
    int row = blockIdx.x * 8 + (threadIdx.x >> 5);
    int lane = threadIdx.x & 31;
    int b = row / N_, n = row % N_;
    if (g_radj[row] <= 0.f) {
        if (lane == 0) g_scnt[row] = 0;
        return;
    }
    float dgn = g_dg[row];
    int cnt = g_ccnt[row], base = row * CSRCAP;
    bool hasdiag = (g_adiag[row] != 0.f);
    float rs = 0.f;
    for (int e = lane; e < cnt; e += 32) {
        int m = g_ccol[base + e];
        int j = g_rank[b * N_ + m];
        if (j >= 0) {
            float ahat = g_cval[base + e] + (m == n ? 1.f : 0.f);
            rs += dgn * ahat * g_dg[b * N_ + m] * g_w[b * ACAP + j];
        }
    }
    if (!hasdiag && lane == 0) {
        int j = g_rank[row];
        if (j >= 0) rs += dgn * dgn * g_w[b * ACAP + j];
    }
    #pragma unroll
    for (int o = 16; o; o >>= 1) rs += __shfl_xor_sync(0xffffffffu, rs, o);
    float inv = 1.f / fmaxf(rs, 1e-12f);
    int sc = 0, sbase = row * SROWCAP;
    for (int c = 0; c < cnt; c += 32) {
        int e = c + lane;
        bool act = false; int j = -1, m = -1; float v = 0.f;
        if (e < cnt) {
            m = g_ccol[base + e];
            j = g_rank[b * N_ + m];
            if (j >= 0) {
                act = true;
                float ahat = g_cval[base + e] + (m == n ? 1.f : 0.f);
                v = dgn * ahat * g_dg[b * N_ + m] * g_w[b * ACAP + j] * inv;
            }
        }
        unsigned msk = __ballot_sync(0xffffffffu, act);
        if (act) {
            int pos = sc + __popc(msk & ((1u << lane) - 1u));
            if (pos < SROWCAP) { g_sj[sbase + pos] = j; g_sv[sbase + pos] = v; }
            S_out[(size_t)row * N_ + m] = v;
        }
        sc += __popc(msk);
    }
    if (!hasdiag) {
        int add = 0;
        if (lane == 0) {
            int j = g_rank[row];
            if (j >= 0) {
                float v = dgn * dgn * g_w[b * ACAP + j] * inv;
                if (sc < SROWCAP) { g_sj[sbase + sc] = j; g_sv[sbase + sc] = v; }
                S_out[(size_t)row * N_ + n] = v;
                add = 1;
            }
        }
        sc += __shfl_sync(0xffffffffu, add, 0);
    }
    if (lane == 0) g_scnt[row] = sc < SROWCAP ? sc : SROWCAP;
}

// ---- KE: T[n,:] = sum_k adj[n,k]*Srow[k]  (warp/row, smem atomics) [R5 exact] ----
__global__ void k_T(){
    int w = threadIdx.x >> 5;
    int row = blockIdx.x * 8 + w;
    int lane = threadIdx.x & 31;
    __shared__ float acc[8][ACAP];
    float* a = acc[w];
    for (int i = lane; i < ACAP; i += 32) a[i] = 0.f;
    __syncwarp();
    int b = row / N_;
    int cnt = g_ccnt[row], base = row * CSRCAP;
    for (int e = lane; e < cnt; e += 32) {
        int k = g_ccol[base + e];
        float av = g_cval[base + e];
        size_t krow = (size_t)b * N_ + k;
        int sb = (int)krow * SROWCAP;
        int sc = g_scnt[krow];
        for (int q = 0; q < sc; q++)
            atomicAdd(&a[g_sj[sb + q]], av * g_sv[sb + q]);
    }
    __syncwarp();
    int A = g_acnt[b];
    float* Trow = g_T + (size_t)row * ACAP;
    for (int j = lane; j < A; j += 32) Trow[j] = a[j];
}

// ---- KF: fused coarse + x_c (scatter into zeroed front) [R5 exact] ----
__global__ void __launch_bounds__(256) k_cx(
        const float* __restrict__ x, const float* __restrict__ S_out,
        float* __restrict__ out_co, float* __restrict__ out_xc){
    int b = blockIdx.y;
    int jm = blockIdx.x;
    int A = g_acnt[b];
    if (jm >= A) return;
    int tid = threadIdx.x;
    int m = g_colid[b * ACAP + jm];
    size_t bN = (size_t)b * N_;
    size_t mrow = bN + m;
    __shared__ int   sn[CSRCAP + 1];
    __shared__ float sv[CSRCAP + 1];
    int cnt = g_ccnt[mrow], base = (int)mrow * CSRCAP;
    if (tid < cnt) {
        int n2 = g_ccol[base + tid];
        sn[tid] = n2;
        sv[tid] = S_out[(bN + n2) * N_ + m];   // symmetry: col m pattern = row m
    }
    int tot = cnt;
    if (g_adiag[mrow] == 0.f) {
        if (tid == 0) { sn[cnt] = m; sv[cnt] = S_out[mrow * N_ + m]; }
        tot = cnt + 1;
    }
    __syncthreads();
    // x_c: tid = feature index (F_ == blockDim.x == 256)
    {
        float acc = 0.f;
        for (int e = 0; e < tot; e++)
            acc += sv[e] * x[(bN + sn[e]) * F_ + tid];
        out_xc[mrow * F_ + tid] = acc;
    }
    // coarse: active block column jm, all active rows j (A <= 256 == blockDim)
    if (tid < A) {
        float acc = 0.f;
        for (int e = 0; e < tot; e++)
            acc += sv[e] * g_T[(bN + sn[e]) * ACAP + tid];
        float c = floorf(acc * 10000.0f) / 10000.0f;
        int l = g_colid[b * ACAP + tid];
        out_co[mrow * N_ + l] = c;
    }
}

extern "C" void kernel_launch(void* const* d_in, const int* in_sizes, int n_in,
                              void* d_out, int out_size) {
    const float* x   = (const float*)d_in[0];
    const float* adj = (const float*)d_in[1];
    const float* W   = (const float*)d_in[2];
    const float* bb  = (const float*)d_in[3];
    float* out = (float*)d_out;

    kA      <<<ROWS_ + 2048, 256>>>(adj, x, W);
    k_alpha <<<2048 + AZB, 256>>>(bb, out + SO_OFF);
    k_topk  <<<B_ + TZB, 1024>>>(out);
    k_sbuild<<<ROWS_ / 8, 256>>>(out + SO_OFF);
    k_T     <<<ROWS_ / 8, 256>>>();
    dim3 gblk(ACAP, B_);
    k_cx    <<<gblk, 256>>>(x, out + SO_OFF, out + CO_OFF, out + XC_OFF);
}